// round 9
// baseline (speedup 1.0000x reference)
#include <cuda_runtime.h>
#include <cuda_fp16.h>

// ---------------------------------------------------------------------------
// CayleyNet: 2x CayleyConv (R=3, K=4 Jacobi) + TopKPooling(0.9) + mean pool + linear
// fp16 storage, fp32 accumulation, jw-folded Jacobi, fused epilogues.
// PERSISTENT conv kernel: all 32 passes in one launch, software grid barrier,
// .cg accesses for cross-pass data (L1 not coherent inside one kernel).
// ---------------------------------------------------------------------------

#define NN    50000
#define EE    800000
#define HH    64
#define HC    32          // lanes per node: lane = 2 complex channels
#define GG    10
#define NPG   5000
#define KKEEP 4500        // ceil(0.9 * 5000)

// ---------------- static device scratch (no allocations allowed) ----------
__device__ int g_cntR[NN];
__device__ int g_cntC[NN];
__device__ int g_rptr[NN + 1];
__device__ int g_cptr[NN + 1];
__device__ unsigned short g_adjR[EE];  // grouped by row: stores col (dst), ids < 65536
__device__ unsigned short g_adjC[EE];  // grouped by col: stores row (src)
__device__ float2 g_jw[NN];            // h * tmp_left[n]
__device__ float2 g_bd[NN];            // b_dia[n]
__device__ uint2  g_BJ[NN * HC];       // b_j (fp16 x4)
__device__ uint2  g_Z0[NN * HC];       // z = jw*y (fp16 x4) ping
__device__ uint2  g_Z1[NN * HC];       // z pong
__device__ uint2  g_Y16[NN * HC];      // final y per order (fp16 x4)
__device__ float2 g_OUT[NN * HC];      // real accumulator (fp32, 2 ch)
__device__ unsigned g_XH[NN * HC];     // fp16 copy of input x (packed half2)
__device__ unsigned g_XR[NN * HC];     // relu'd features (packed half2)
__device__ float  g_S[NN];             // topk scores
__device__ float g_pool[GG * HH];
__device__ unsigned g_barA;            // barrier arrival counter
__device__ volatile unsigned g_barG;   // barrier generation

// register-friendly reinterpret helpers
union H4U { uint2 u; __half2 h[2]; };
union H2U { unsigned u; __half2 h; };

__device__ __forceinline__ float4 h4_to_f4(uint2 v) {
    H4U c; c.u = v;
    float2 fa = __half22float2(c.h[0]);
    float2 fb = __half22float2(c.h[1]);
    return make_float4(fa.x, fa.y, fb.x, fb.y);
}
__device__ __forceinline__ uint2 f4_to_h4(float4 f) {
    H4U c;
    c.h[0] = __float22half2_rn(make_float2(f.x, f.y));
    c.h[1] = __float22half2_rn(make_float2(f.z, f.w));
    return c.u;
}
__device__ __forceinline__ float2 h2_to_f2(unsigned v) {
    H2U c; c.u = v;
    return __half22float2(c.h);
}
__device__ __forceinline__ unsigned f2_to_h2(float2 f) {
    H2U c; c.h = __float22half2_rn(f);
    return c.u;
}

// software grid barrier: fenced arrival + generation poll (L2, volatile)
__device__ __forceinline__ void gbar(unsigned target, unsigned nb) {
    __syncthreads();
    if (threadIdx.x == 0) {
        __threadfence();
        unsigned a = atomicAdd(&g_barA, 1u);
        if (a == nb - 1u) {
            g_barA = 0u;
            __threadfence();
            atomicExch((unsigned*)&g_barG, target);
        } else {
            while (*(volatile unsigned*)&g_barG < target) __nanosleep(64);
        }
    }
    __syncthreads();
}

// ---------------- CSR construction ----------------------------------------
__global__ void k_zero() {
    int i = blockIdx.x * blockDim.x + threadIdx.x;
    if (i == 0) { g_barA = 0u; *(unsigned*)&g_barG = 0u; }
    for (; i < NN; i += gridDim.x * blockDim.x) {
        g_cntR[i] = 0;
        g_cntC[i] = 0;
    }
}

__global__ void k_hist(const int* __restrict__ ei) {
    for (int e = blockIdx.x * blockDim.x + threadIdx.x; e < EE; e += gridDim.x * blockDim.x) {
        atomicAdd(&g_cntR[ei[e]], 1);
        atomicAdd(&g_cntC[ei[EE + e]], 1);
    }
}

// 2 blocks: block 0 scans cntR->rptr, block 1 scans cntC->cptr.
// Also rewrites cnt[i] = start offset (fill cursor).
__global__ void k_scan() {
    __shared__ int sm[1024];
    const int PER = 49;
    int which = blockIdx.x;
    int* cnt = which ? g_cntC : g_cntR;
    int* ptr = which ? g_cptr : g_rptr;
    int t = threadIdx.x;
    int base = t * PER;
    int local = 0;
    for (int i = 0; i < PER; ++i) {
        int idx = base + i;
        if (idx < NN) local += cnt[idx];
    }
    sm[t] = local;
    __syncthreads();
    for (int off = 1; off < 1024; off <<= 1) {
        int v = (t >= off) ? sm[t - off] : 0;
        __syncthreads();
        sm[t] += v;
        __syncthreads();
    }
    int run = sm[t] - local;
    for (int i = 0; i < PER; ++i) {
        int idx = base + i;
        if (idx < NN) {
            int c = cnt[idx];
            ptr[idx] = run;
            cnt[idx] = run;     // cursor for k_fill
            run += c;
        }
    }
    if (t == 1023) ptr[NN] = sm[1023];
}

__global__ void k_fill(const int* __restrict__ ei) {
    for (int e = blockIdx.x * blockDim.x + threadIdx.x; e < EE; e += gridDim.x * blockDim.x) {
        int r = ei[e];
        int c = ei[EE + e];
        g_adjR[atomicAdd(&g_cntR[r], 1)] = (unsigned short)c;
        g_adjC[atomicAdd(&g_cntC[c], 1)] = (unsigned short)r;
    }
}

// ---------------- x -> fp16 copy -------------------------------------------
__global__ void k_x2h(const float* __restrict__ x) {
    for (int i = blockIdx.x * blockDim.x + threadIdx.x; i < NN * HC; i += gridDim.x * blockDim.x) {
        float2 v = ((const float2*)x)[i];
        g_XH[i] = f2_to_h2(v);
    }
}

// ---------------- persistent conv kernel -----------------------------------
__global__ void __launch_bounds__(256, 4)
k_conv(const float* __restrict__ h, const float* __restrict__ alpha,
       const float* __restrict__ c0, const float* __restrict__ cj,
       const float* __restrict__ tw) {
    const int tidg = blockIdx.x * 256 + threadIdx.x;
    const int NT = gridDim.x * 256;
    const int wg = tidg >> 5;
    const int NW = NT >> 5;
    const int lane = threadIdx.x & 31;
    const unsigned nb = gridDim.x;
    unsigned bt = 0;

    for (int l = 0; l < 2; ++l) {
        float hv = __ldg(&h[l]), av = __ldg(&alpha[l]);
        // ---- pass: per-layer node params ----
        for (int n = tidg; n < NN; n += NT) {
            float deg = (float)(__ldg(&g_rptr[n + 1]) - __ldg(&g_rptr[n]));
            float a = hv * (deg - av);
            float inv = 1.0f / (a * a + 1.0f);
            __stcg(&g_jw[n], make_float2(hv * a * inv, -hv * inv));
            __stcg(&g_bd[n], make_float2((a * a - 1.0f) * inv, -2.0f * a * inv));
        }
        gbar(++bt, nb);

        for (int j = 0; j < 3; ++j) {
            // ---- pass: b_j ----
            if (j == 0) {
                const unsigned* __restrict__ X = l ? g_XR : g_XH;
                float c0v = __ldg(&c0[l]);
                for (int n = wg; n < NN; n += NW) {
                    int p = __ldg(&g_rptr[n]), end = __ldg(&g_rptr[n + 1]);
                    float sx = 0.f, sy = 0.f;
                    for (; p + 8 <= end; p += 8) {
                        int d0 = __ldg(&g_adjR[p + 0]), d1 = __ldg(&g_adjR[p + 1]);
                        int d2 = __ldg(&g_adjR[p + 2]), d3 = __ldg(&g_adjR[p + 3]);
                        int d4 = __ldg(&g_adjR[p + 4]), d5 = __ldg(&g_adjR[p + 5]);
                        int d6 = __ldg(&g_adjR[p + 6]), d7 = __ldg(&g_adjR[p + 7]);
                        float2 f0 = h2_to_f2(__ldcg(&X[d0 * HC + lane]));
                        float2 f1 = h2_to_f2(__ldcg(&X[d1 * HC + lane]));
                        float2 f2 = h2_to_f2(__ldcg(&X[d2 * HC + lane]));
                        float2 f3 = h2_to_f2(__ldcg(&X[d3 * HC + lane]));
                        float2 f4 = h2_to_f2(__ldcg(&X[d4 * HC + lane]));
                        float2 f5 = h2_to_f2(__ldcg(&X[d5 * HC + lane]));
                        float2 f6 = h2_to_f2(__ldcg(&X[d6 * HC + lane]));
                        float2 f7 = h2_to_f2(__ldcg(&X[d7 * HC + lane]));
                        sx += f0.x + f1.x + f2.x + f3.x + f4.x + f5.x + f6.x + f7.x;
                        sy += f0.y + f1.y + f2.y + f3.y + f4.y + f5.y + f6.y + f7.y;
                    }
                    for (; p < end; ++p) {
                        int d = __ldg(&g_adjR[p]);
                        float2 f = h2_to_f2(__ldcg(&X[d * HC + lane]));
                        sx += f.x;
                        sy += f.y;
                    }
                    float2 jwv = __ldcg(&g_jw[n]);
                    float wnx = -jwv.x, wny = -jwv.y;
                    float2 bdv = __ldcg(&g_bd[n]);
                    float2 vn = h2_to_f2(__ldcg(&X[n * HC + lane]));
                    float4 b;
                    b.x = wnx * sx + bdv.x * vn.x;
                    b.y = wny * sx + bdv.y * vn.x;
                    b.z = wnx * sy + bdv.x * vn.y;
                    b.w = wny * sy + bdv.y * vn.y;
                    int idx = n * HC + lane;
                    __stcg(&g_BJ[idx], f4_to_h4(b));
                    float4 z;                      // z0 = jw * b
                    z.x = jwv.x * b.x - jwv.y * b.y;
                    z.y = jwv.x * b.y + jwv.y * b.x;
                    z.z = jwv.x * b.z - jwv.y * b.w;
                    z.w = jwv.x * b.w + jwv.y * b.z;
                    __stcg(&g_Z0[idx], f4_to_h4(z));
                    __stcg(&g_OUT[idx], make_float2(c0v * vn.x, c0v * vn.y));
                }
            } else {
                for (int n = wg; n < NN; n += NW) {
                    int p = __ldg(&g_rptr[n]), end = __ldg(&g_rptr[n + 1]);
                    float4 a = make_float4(0.f, 0.f, 0.f, 0.f);
                    for (; p + 8 <= end; p += 8) {
                        int d0 = __ldg(&g_adjR[p + 0]), d1 = __ldg(&g_adjR[p + 1]);
                        int d2 = __ldg(&g_adjR[p + 2]), d3 = __ldg(&g_adjR[p + 3]);
                        int d4 = __ldg(&g_adjR[p + 4]), d5 = __ldg(&g_adjR[p + 5]);
                        int d6 = __ldg(&g_adjR[p + 6]), d7 = __ldg(&g_adjR[p + 7]);
                        float4 v0 = h4_to_f4(__ldcg(&g_Y16[d0 * HC + lane]));
                        float4 v1 = h4_to_f4(__ldcg(&g_Y16[d1 * HC + lane]));
                        float4 v2 = h4_to_f4(__ldcg(&g_Y16[d2 * HC + lane]));
                        float4 v3 = h4_to_f4(__ldcg(&g_Y16[d3 * HC + lane]));
                        float4 v4 = h4_to_f4(__ldcg(&g_Y16[d4 * HC + lane]));
                        float4 v5 = h4_to_f4(__ldcg(&g_Y16[d5 * HC + lane]));
                        float4 v6 = h4_to_f4(__ldcg(&g_Y16[d6 * HC + lane]));
                        float4 v7 = h4_to_f4(__ldcg(&g_Y16[d7 * HC + lane]));
                        a.x += v0.x + v1.x + v2.x + v3.x + v4.x + v5.x + v6.x + v7.x;
                        a.y += v0.y + v1.y + v2.y + v3.y + v4.y + v5.y + v6.y + v7.y;
                        a.z += v0.z + v1.z + v2.z + v3.z + v4.z + v5.z + v6.z + v7.z;
                        a.w += v0.w + v1.w + v2.w + v3.w + v4.w + v5.w + v6.w + v7.w;
                    }
                    for (; p < end; ++p) {
                        int d = __ldg(&g_adjR[p]);
                        float4 v = h4_to_f4(__ldcg(&g_Y16[d * HC + lane]));
                        a.x += v.x; a.y += v.y; a.z += v.z; a.w += v.w;
                    }
                    float2 jwv = __ldcg(&g_jw[n]);
                    float wnx = -jwv.x, wny = -jwv.y;
                    float2 bdv = __ldcg(&g_bd[n]);
                    int idx = n * HC + lane;
                    float4 vn = h4_to_f4(__ldcg(&g_Y16[idx]));
                    float4 b;
                    b.x = wnx * a.x - wny * a.y + bdv.x * vn.x - bdv.y * vn.y;
                    b.y = wnx * a.y + wny * a.x + bdv.x * vn.y + bdv.y * vn.x;
                    b.z = wnx * a.z - wny * a.w + bdv.x * vn.z - bdv.y * vn.w;
                    b.w = wnx * a.w + wny * a.z + bdv.x * vn.w + bdv.y * vn.z;
                    __stcg(&g_BJ[idx], f4_to_h4(b));
                    float4 z;
                    z.x = jwv.x * b.x - jwv.y * b.y;
                    z.y = jwv.x * b.y + jwv.y * b.x;
                    z.z = jwv.x * b.z - jwv.y * b.w;
                    z.w = jwv.x * b.w + jwv.y * b.z;
                    __stcg(&g_Z0[idx], f4_to_h4(z));
                }
            }
            gbar(++bt, nb);

            // ---- 4 jacobi passes ----
            int cjoff = (l * 3 + j) * 2;
            float cr = __ldg(&cj[cjoff]), ci = __ldg(&cj[cjoff + 1]);
            for (int k = 0; k < 4; ++k) {
                const uint2* __restrict__ Zin = (k & 1) ? g_Z1 : g_Z0;
                uint2* __restrict__ Zout = (k & 1) ? g_Z0 : g_Z1;
                bool fin = (k == 3);
                bool last = fin && (j == 2);
                bool scor = last && (l == 1);
                for (int n = wg; n < NN; n += NW) {
                    int p = __ldg(&g_cptr[n]), end = __ldg(&g_cptr[n + 1]);
                    float4 acc = make_float4(0.f, 0.f, 0.f, 0.f);
                    for (; p + 8 <= end; p += 8) {
                        int s0 = __ldg(&g_adjC[p + 0]), s1 = __ldg(&g_adjC[p + 1]);
                        int s2 = __ldg(&g_adjC[p + 2]), s3 = __ldg(&g_adjC[p + 3]);
                        int s4 = __ldg(&g_adjC[p + 4]), s5 = __ldg(&g_adjC[p + 5]);
                        int s6 = __ldg(&g_adjC[p + 6]), s7 = __ldg(&g_adjC[p + 7]);
                        float4 v0 = h4_to_f4(__ldcg(&Zin[s0 * HC + lane]));
                        float4 v1 = h4_to_f4(__ldcg(&Zin[s1 * HC + lane]));
                        float4 v2 = h4_to_f4(__ldcg(&Zin[s2 * HC + lane]));
                        float4 v3 = h4_to_f4(__ldcg(&Zin[s3 * HC + lane]));
                        float4 v4 = h4_to_f4(__ldcg(&Zin[s4 * HC + lane]));
                        float4 v5 = h4_to_f4(__ldcg(&Zin[s5 * HC + lane]));
                        float4 v6 = h4_to_f4(__ldcg(&Zin[s6 * HC + lane]));
                        float4 v7 = h4_to_f4(__ldcg(&Zin[s7 * HC + lane]));
                        acc.x += v0.x + v1.x + v2.x + v3.x + v4.x + v5.x + v6.x + v7.x;
                        acc.y += v0.y + v1.y + v2.y + v3.y + v4.y + v5.y + v6.y + v7.y;
                        acc.z += v0.z + v1.z + v2.z + v3.z + v4.z + v5.z + v6.z + v7.z;
                        acc.w += v0.w + v1.w + v2.w + v3.w + v4.w + v5.w + v6.w + v7.w;
                    }
                    for (; p < end; ++p) {
                        int s = __ldg(&g_adjC[p]);
                        float4 v = h4_to_f4(__ldcg(&Zin[s * HC + lane]));
                        acc.x += v.x; acc.y += v.y; acc.z += v.z; acc.w += v.w;
                    }
                    int idx = n * HC + lane;
                    float4 b = h4_to_f4(__ldcg(&g_BJ[idx]));
                    acc.x += b.x; acc.y += b.y; acc.z += b.z; acc.w += b.w;
                    if (!fin) {
                        float2 jwv = __ldcg(&g_jw[n]);
                        float4 z;
                        z.x = jwv.x * acc.x - jwv.y * acc.y;
                        z.y = jwv.x * acc.y + jwv.y * acc.x;
                        z.z = jwv.x * acc.z - jwv.y * acc.w;
                        z.w = jwv.x * acc.w + jwv.y * acc.z;
                        __stcg(&Zout[idx], f4_to_h4(z));
                    } else {
                        float2 o = __ldcg(&g_OUT[idx]);
                        o.x += 2.0f * (cr * acc.x - ci * acc.y);
                        o.y += 2.0f * (cr * acc.z - ci * acc.w);
                        if (!last) {
                            __stcg(&g_Y16[idx], f4_to_h4(acc));
                            __stcg(&g_OUT[idx], o);
                        } else {
                            float2 xr = make_float2(fmaxf(o.x, 0.f), fmaxf(o.y, 0.f));
                            __stcg(&g_XR[idx], f2_to_h2(xr));
                            if (scor) {
                                float2 wv = __ldg(&((const float2*)tw)[lane]);
                                float dot = xr.x * wv.x + xr.y * wv.y;
                                float nsq = wv.x * wv.x + wv.y * wv.y;
                                for (int off = 16; off > 0; off >>= 1) {
                                    dot += __shfl_xor_sync(0xFFFFFFFFu, dot, off);
                                    nsq += __shfl_xor_sync(0xFFFFFFFFu, nsq, off);
                                }
                                if (lane == 0) __stcg(&g_S[n], tanhf(dot * rsqrtf(nsq)));
                            }
                        }
                    }
                }
                if (!(l == 1 && j == 2 && k == 3))
                    gbar(++bt, nb);
            }
        }
    }
}

__device__ __forceinline__ unsigned long long make_key(float f, int idx) {
    unsigned u = __float_as_uint(f);
    u = (u & 0x80000000u) ? ~u : (u | 0x80000000u);
    return ((unsigned long long)u << 32) | (unsigned)(0xFFFFFFFFu - (unsigned)idx);
}

// ---------------- fused tail: per-graph radix-select + pool + linear -------
__global__ void k_tail(const float* __restrict__ lw, const float* __restrict__ lb,
                       float* __restrict__ out) {
    __shared__ int hist[256];
    __shared__ float sm[256];
    __shared__ float pooled[HH];
    __shared__ unsigned long long s_prefix;
    __shared__ int s_kk;
    int g = blockIdx.x;
    int t = threadIdx.x;

    if (t == 0) { s_prefix = 0ULL; s_kk = KKEEP; }
    __syncthreads();
    for (int pass = 7; pass >= 0; --pass) {
        int shift = pass * 8;
        hist[t] = 0;
        __syncthreads();
        unsigned long long pfx = s_prefix;
        unsigned long long maskhi = (pass == 7) ? 0ULL : ((~0ULL) << (shift + 8));
        for (int i = t; i < NPG; i += 256) {
            unsigned long long key = make_key(g_S[g * NPG + i], i);
            if ((key & maskhi) == (pfx & maskhi))
                atomicAdd(&hist[(int)((key >> shift) & 0xFF)], 1);
        }
        __syncthreads();
        if (t == 0) {
            int kk = s_kk;
            int bb = 255;
            for (;;) {
                int c = hist[bb];
                if (c >= kk) break;
                kk -= c;
                --bb;
            }
            s_kk = kk;
            s_prefix = pfx | ((unsigned long long)bb << shift);
        }
        __syncthreads();
    }
    unsigned long long thr = s_prefix;

    int ch = t & 63;
    int nl = t >> 6;
    float acc = 0.f;
    for (int i = nl; i < NPG; i += 4) {
        int node = g * NPG + i;
        float sv = g_S[node];
        if (make_key(sv, i) >= thr) {
            float2 f = h2_to_f2(g_XR[node * HC + (ch >> 1)]);
            acc += ((ch & 1) ? f.y : f.x) * sv;
        }
    }
    sm[t] = acc;
    __syncthreads();
    if (nl == 0)
        pooled[ch] = (sm[ch] + sm[64 + ch] + sm[128 + ch] + sm[192 + ch]) * (1.0f / (float)KKEEP);
    __syncthreads();

    if (t < 10) {
        float a = __ldg(&lb[t]);
        #pragma unroll
        for (int hh = 0; hh < HH; ++hh)
            a += pooled[hh] * __ldg(&lw[hh * 10 + t]);
        out[g * 10 + t] = a;
    }
}

// ---------------------------------------------------------------------------
extern "C" void kernel_launch(void* const* d_in, const int* in_sizes, int n_in,
                              void* d_out, int out_size) {
    const float* x     = (const float*)d_in[0];
    const int*   ei    = (const int*)d_in[1];
    const float* h     = (const float*)d_in[3];
    const float* alpha = (const float*)d_in[4];
    const float* c0    = (const float*)d_in[5];
    const float* cj    = (const float*)d_in[6];
    const float* tw    = (const float*)d_in[7];
    const float* lw    = (const float*)d_in[8];
    const float* lb    = (const float*)d_in[9];
    float* out = (float*)d_out;

    int dev = 0, nsm = 148;
    cudaGetDevice(&dev);
    cudaDeviceGetAttribute(&nsm, cudaDevAttrMultiProcessorCount, dev);
    int NB = nsm * 4;   // co-residency guaranteed by __launch_bounds__(256, 4)

    // CSR build (both directions) + barrier state reset
    k_zero<<<196, 256>>>();
    k_hist<<<1024, 256>>>(ei);
    k_scan<<<2, 1024>>>();
    k_fill<<<1024, 256>>>(ei);
    k_x2h<<<1024, 256>>>(x);

    // whole 2-layer conv in one persistent kernel
    k_conv<<<NB, 256>>>(h, alpha, c0, cj, tw);

    k_tail<<<GG, 256>>>(lw, lb, out);
}

// round 10
// speedup vs baseline: 1.0223x; 1.0223x over previous
#include <cuda_runtime.h>
#include <cuda_fp16.h>

// ---------------------------------------------------------------------------
// CayleyNet: 2x CayleyConv (R=3, K=4 Jacobi) + TopKPooling(0.9) + mean pool + linear
// fp16 storage (z, y, BJ, x), fp32 accumulation, jw-folded Jacobi,
// fused relu/scores epilogues, identity scheduling, uint16 adjacency,
// precomputed per-layer params, grid-stride SpMM kernels, fused tail.
// ---------------------------------------------------------------------------

#define NN    50000
#define EE    800000
#define HH    64
#define HC    32          // lanes per node: lane = 2 complex channels
#define GG    10
#define NPG   5000
#define KKEEP 4500        // ceil(0.9 * 5000)

// ---------------- static device scratch (no allocations allowed) ----------
__device__ int g_cntR[NN];
__device__ int g_cntC[NN];
__device__ int g_rptr[NN + 1];
__device__ int g_cptr[NN + 1];
__device__ unsigned short g_adjR[EE];  // grouped by row: stores col (dst), ids < 65536
__device__ unsigned short g_adjC[EE];  // grouped by col: stores row (src)
__device__ float2 g_jw[NN];            // h * tmp_left[n]
__device__ float2 g_bd[NN];            // b_dia[n]
__device__ uint2  g_BJ[NN * HC];       // b_j (fp16 x4)
__device__ uint2  g_Z0[NN * HC];       // z = jw*y (fp16 x4) ping
__device__ uint2  g_Z1[NN * HC];       // z pong
__device__ uint2  g_Y16[NN * HC];      // final y per order (fp16 x4)
__device__ float2 g_OUT[NN * HC];      // real accumulator (fp32, 2 ch)
__device__ unsigned g_XH[NN * HC];     // fp16 copy of input x (packed half2)
__device__ unsigned g_XR[NN * HC];     // relu'd features (packed half2)
__device__ float  g_S[NN];             // topk scores
__device__ float g_pool[GG * HH];

__device__ __forceinline__ uint2* zbuf(int s) { return s ? g_Z1 : g_Z0; }

// register-friendly reinterpret helpers
union H4U { uint2 u; __half2 h[2]; };
union H2U { unsigned u; __half2 h; };

__device__ __forceinline__ float4 h4_to_f4(uint2 v) {
    H4U c; c.u = v;
    float2 fa = __half22float2(c.h[0]);
    float2 fb = __half22float2(c.h[1]);
    return make_float4(fa.x, fa.y, fb.x, fb.y);
}
__device__ __forceinline__ uint2 f4_to_h4(float4 f) {
    H4U c;
    c.h[0] = __float22half2_rn(make_float2(f.x, f.y));
    c.h[1] = __float22half2_rn(make_float2(f.z, f.w));
    return c.u;
}
__device__ __forceinline__ float2 h2_to_f2(unsigned v) {
    H2U c; c.u = v;
    return __half22float2(c.h);
}
__device__ __forceinline__ unsigned f2_to_h2(float2 f) {
    H2U c; c.h = __float22half2_rn(f);
    return c.u;
}

// ---------------- CSR init + x->fp16 (merged) ------------------------------
__global__ void k_zero(const float* __restrict__ x) {
    int stride = gridDim.x * blockDim.x;
    int i = blockIdx.x * blockDim.x + threadIdx.x;
    for (; i < NN * HC; i += stride) {
        if (i < NN) { g_cntR[i] = 0; g_cntC[i] = 0; }
        float2 v = ((const float2*)x)[i];
        g_XH[i] = f2_to_h2(v);
    }
}

__global__ void k_hist(const int* __restrict__ ei) {
    for (int e = blockIdx.x * blockDim.x + threadIdx.x; e < EE; e += gridDim.x * blockDim.x) {
        atomicAdd(&g_cntR[ei[e]], 1);
        atomicAdd(&g_cntC[ei[EE + e]], 1);
    }
}

// 2 blocks: block 0 scans cntR->rptr, block 1 scans cntC->cptr.
// Also rewrites cnt[i] = start offset (fill cursor).
__global__ void k_scan() {
    __shared__ int sm[1024];
    const int PER = 49;
    int which = blockIdx.x;
    int* cnt = which ? g_cntC : g_cntR;
    int* ptr = which ? g_cptr : g_rptr;
    int t = threadIdx.x;
    int base = t * PER;
    int local = 0;
    for (int i = 0; i < PER; ++i) {
        int idx = base + i;
        if (idx < NN) local += cnt[idx];
    }
    sm[t] = local;
    __syncthreads();
    for (int off = 1; off < 1024; off <<= 1) {
        int v = (t >= off) ? sm[t - off] : 0;
        __syncthreads();
        sm[t] += v;
        __syncthreads();
    }
    int run = sm[t] - local;
    for (int i = 0; i < PER; ++i) {
        int idx = base + i;
        if (idx < NN) {
            int c = cnt[idx];
            ptr[idx] = run;
            cnt[idx] = run;     // cursor for k_fill
            run += c;
        }
    }
    if (t == 1023) ptr[NN] = sm[1023];
}

__global__ void k_fill(const int* __restrict__ ei) {
    for (int e = blockIdx.x * blockDim.x + threadIdx.x; e < EE; e += gridDim.x * blockDim.x) {
        int r = ei[e];
        int c = ei[EE + e];
        g_adjR[atomicAdd(&g_cntR[r], 1)] = (unsigned short)c;
        g_adjC[atomicAdd(&g_cntC[c], 1)] = (unsigned short)r;
    }
}

// ---------------- per-layer node parameters --------------------------------
__global__ void k_params(const float* __restrict__ h, const float* __restrict__ alpha, int l) {
    float hv = h[l], av = alpha[l];
    for (int n = blockIdx.x * blockDim.x + threadIdx.x; n < NN; n += gridDim.x * blockDim.x) {
        float deg = (float)(g_rptr[n + 1] - g_rptr[n]);
        float a = hv * (deg - av);
        float inv = 1.0f / (a * a + 1.0f);
        g_jw[n] = make_float2(hv * a * inv, -hv * inv);
        g_bd[n] = make_float2((a * a - 1.0f) * inv, -2.0f * a * inv);
    }
}

// ---------------- b_j from REAL fp16 input (j==0): also init OUT, Z0 -------
__global__ void k_bj_real(int use_xr, const float* __restrict__ c0, int l) {
    int wg = (blockIdx.x * blockDim.x + threadIdx.x) >> 5;
    int NW = (gridDim.x * blockDim.x) >> 5;
    int lane = threadIdx.x & 31;
    const unsigned* __restrict__ X = use_xr ? g_XR : g_XH;
    for (int n = wg; n < NN; n += NW) {
        int p = g_rptr[n], end = g_rptr[n + 1];
        float sx = 0.f, sy = 0.f;
        for (; p + 8 <= end; p += 8) {
            int d0 = __ldg(&g_adjR[p + 0]), d1 = __ldg(&g_adjR[p + 1]);
            int d2 = __ldg(&g_adjR[p + 2]), d3 = __ldg(&g_adjR[p + 3]);
            int d4 = __ldg(&g_adjR[p + 4]), d5 = __ldg(&g_adjR[p + 5]);
            int d6 = __ldg(&g_adjR[p + 6]), d7 = __ldg(&g_adjR[p + 7]);
            float2 f0 = h2_to_f2(__ldg(&X[d0 * HC + lane]));
            float2 f1 = h2_to_f2(__ldg(&X[d1 * HC + lane]));
            float2 f2 = h2_to_f2(__ldg(&X[d2 * HC + lane]));
            float2 f3 = h2_to_f2(__ldg(&X[d3 * HC + lane]));
            float2 f4 = h2_to_f2(__ldg(&X[d4 * HC + lane]));
            float2 f5 = h2_to_f2(__ldg(&X[d5 * HC + lane]));
            float2 f6 = h2_to_f2(__ldg(&X[d6 * HC + lane]));
            float2 f7 = h2_to_f2(__ldg(&X[d7 * HC + lane]));
            sx += f0.x + f1.x + f2.x + f3.x + f4.x + f5.x + f6.x + f7.x;
            sy += f0.y + f1.y + f2.y + f3.y + f4.y + f5.y + f6.y + f7.y;
        }
        for (; p < end; ++p) {
            int d = __ldg(&g_adjR[p]);
            float2 f = h2_to_f2(__ldg(&X[d * HC + lane]));
            sx += f.x;
            sy += f.y;
        }
        float2 jwv = g_jw[n];
        float wnx = -jwv.x, wny = -jwv.y;
        float2 bdv = g_bd[n];
        float2 vn = h2_to_f2(__ldg(&X[n * HC + lane]));
        float4 b;
        b.x = wnx * sx + bdv.x * vn.x;
        b.y = wny * sx + bdv.y * vn.x;
        b.z = wnx * sy + bdv.x * vn.y;
        b.w = wny * sy + bdv.y * vn.y;
        int idx = n * HC + lane;
        g_BJ[idx] = f4_to_h4(b);
        float4 z;                              // z0 = jw * b
        z.x = jwv.x * b.x - jwv.y * b.y;
        z.y = jwv.x * b.y + jwv.y * b.x;
        z.z = jwv.x * b.z - jwv.y * b.w;
        z.w = jwv.x * b.w + jwv.y * b.z;
        g_Z0[idx] = f4_to_h4(z);
        float c0v = __ldg(&c0[l]);
        g_OUT[idx] = make_float2(c0v * vn.x, c0v * vn.y);
    }
}

// ---------------- b_j from COMPLEX fp16 input (j>0): reads Y16 -------------
__global__ void k_bj_cplx() {
    int wg = (blockIdx.x * blockDim.x + threadIdx.x) >> 5;
    int NW = (gridDim.x * blockDim.x) >> 5;
    int lane = threadIdx.x & 31;
    for (int n = wg; n < NN; n += NW) {
        int p = g_rptr[n], end = g_rptr[n + 1];
        float4 a = make_float4(0.f, 0.f, 0.f, 0.f);
        for (; p + 8 <= end; p += 8) {
            int d0 = __ldg(&g_adjR[p + 0]), d1 = __ldg(&g_adjR[p + 1]);
            int d2 = __ldg(&g_adjR[p + 2]), d3 = __ldg(&g_adjR[p + 3]);
            int d4 = __ldg(&g_adjR[p + 4]), d5 = __ldg(&g_adjR[p + 5]);
            int d6 = __ldg(&g_adjR[p + 6]), d7 = __ldg(&g_adjR[p + 7]);
            float4 v0 = h4_to_f4(__ldg(&g_Y16[d0 * HC + lane]));
            float4 v1 = h4_to_f4(__ldg(&g_Y16[d1 * HC + lane]));
            float4 v2 = h4_to_f4(__ldg(&g_Y16[d2 * HC + lane]));
            float4 v3 = h4_to_f4(__ldg(&g_Y16[d3 * HC + lane]));
            float4 v4 = h4_to_f4(__ldg(&g_Y16[d4 * HC + lane]));
            float4 v5 = h4_to_f4(__ldg(&g_Y16[d5 * HC + lane]));
            float4 v6 = h4_to_f4(__ldg(&g_Y16[d6 * HC + lane]));
            float4 v7 = h4_to_f4(__ldg(&g_Y16[d7 * HC + lane]));
            a.x += v0.x + v1.x + v2.x + v3.x + v4.x + v5.x + v6.x + v7.x;
            a.y += v0.y + v1.y + v2.y + v3.y + v4.y + v5.y + v6.y + v7.y;
            a.z += v0.z + v1.z + v2.z + v3.z + v4.z + v5.z + v6.z + v7.z;
            a.w += v0.w + v1.w + v2.w + v3.w + v4.w + v5.w + v6.w + v7.w;
        }
        for (; p < end; ++p) {
            int d = __ldg(&g_adjR[p]);
            float4 v = h4_to_f4(__ldg(&g_Y16[d * HC + lane]));
            a.x += v.x; a.y += v.y; a.z += v.z; a.w += v.w;
        }
        float2 jwv = g_jw[n];
        float wnx = -jwv.x, wny = -jwv.y;
        float2 bdv = g_bd[n];
        int idx = n * HC + lane;
        float4 vn = h4_to_f4(g_Y16[idx]);
        float4 b;
        b.x = wnx * a.x - wny * a.y + bdv.x * vn.x - bdv.y * vn.y;
        b.y = wnx * a.y + wny * a.x + bdv.x * vn.y + bdv.y * vn.x;
        b.z = wnx * a.z - wny * a.w + bdv.x * vn.z - bdv.y * vn.w;
        b.w = wnx * a.w + wny * a.z + bdv.x * vn.w + bdv.y * vn.z;
        g_BJ[idx] = f4_to_h4(b);
        float4 z;
        z.x = jwv.x * b.x - jwv.y * b.y;
        z.y = jwv.x * b.y + jwv.y * b.x;
        z.z = jwv.x * b.z - jwv.y * b.w;
        z.w = jwv.x * b.w + jwv.y * b.z;
        g_Z0[idx] = f4_to_h4(z);
    }
}

// ---------------- jacobi: y[n] = sum_{e:col=n} z[src] + b_j[n] -------------
// FINAL=false: write z_out = jw*y.
// FINAL,!LAST: write Y16=y, OUT += 2*Re(cj*y).
// FINAL,LAST : o = OUT + 2*Re(cj*y); XR = relu(o) fp16; SCORES: also g_S.
template <bool FINAL, bool LAST, bool SCORES>
__global__ void k_jac(int in_sel, int out_sel, const float* __restrict__ cj, int cjoff,
                      const float* __restrict__ tw) {
    int wg = (blockIdx.x * blockDim.x + threadIdx.x) >> 5;
    int NW = (gridDim.x * blockDim.x) >> 5;
    int lane = threadIdx.x & 31;
    const uint2* __restrict__ Zin = zbuf(in_sel);
    for (int n = wg; n < NN; n += NW) {
        int p = g_cptr[n], end = g_cptr[n + 1];
        float4 acc = make_float4(0.f, 0.f, 0.f, 0.f);
        for (; p + 8 <= end; p += 8) {
            int s0 = __ldg(&g_adjC[p + 0]), s1 = __ldg(&g_adjC[p + 1]);
            int s2 = __ldg(&g_adjC[p + 2]), s3 = __ldg(&g_adjC[p + 3]);
            int s4 = __ldg(&g_adjC[p + 4]), s5 = __ldg(&g_adjC[p + 5]);
            int s6 = __ldg(&g_adjC[p + 6]), s7 = __ldg(&g_adjC[p + 7]);
            float4 v0 = h4_to_f4(__ldg(&Zin[s0 * HC + lane]));
            float4 v1 = h4_to_f4(__ldg(&Zin[s1 * HC + lane]));
            float4 v2 = h4_to_f4(__ldg(&Zin[s2 * HC + lane]));
            float4 v3 = h4_to_f4(__ldg(&Zin[s3 * HC + lane]));
            float4 v4 = h4_to_f4(__ldg(&Zin[s4 * HC + lane]));
            float4 v5 = h4_to_f4(__ldg(&Zin[s5 * HC + lane]));
            float4 v6 = h4_to_f4(__ldg(&Zin[s6 * HC + lane]));
            float4 v7 = h4_to_f4(__ldg(&Zin[s7 * HC + lane]));
            acc.x += v0.x + v1.x + v2.x + v3.x + v4.x + v5.x + v6.x + v7.x;
            acc.y += v0.y + v1.y + v2.y + v3.y + v4.y + v5.y + v6.y + v7.y;
            acc.z += v0.z + v1.z + v2.z + v3.z + v4.z + v5.z + v6.z + v7.z;
            acc.w += v0.w + v1.w + v2.w + v3.w + v4.w + v5.w + v6.w + v7.w;
        }
        for (; p < end; ++p) {
            int s = __ldg(&g_adjC[p]);
            float4 v = h4_to_f4(__ldg(&Zin[s * HC + lane]));
            acc.x += v.x; acc.y += v.y; acc.z += v.z; acc.w += v.w;
        }
        int idx = n * HC + lane;
        float4 b = h4_to_f4(g_BJ[idx]);
        acc.x += b.x; acc.y += b.y; acc.z += b.z; acc.w += b.w;   // acc = y
        if (!FINAL) {
            float2 jwv = g_jw[n];
            float4 z;
            z.x = jwv.x * acc.x - jwv.y * acc.y;
            z.y = jwv.x * acc.y + jwv.y * acc.x;
            z.z = jwv.x * acc.z - jwv.y * acc.w;
            z.w = jwv.x * acc.w + jwv.y * acc.z;
            zbuf(out_sel)[idx] = f4_to_h4(z);
        } else {
            float cr = __ldg(&cj[cjoff]), ci = __ldg(&cj[cjoff + 1]);
            float2 o = g_OUT[idx];
            o.x += 2.0f * (cr * acc.x - ci * acc.y);
            o.y += 2.0f * (cr * acc.z - ci * acc.w);
            if (!LAST) {
                g_Y16[idx] = f4_to_h4(acc);
                g_OUT[idx] = o;
            } else {
                float2 xr = make_float2(fmaxf(o.x, 0.f), fmaxf(o.y, 0.f));
                g_XR[idx] = f2_to_h2(xr);
                if (SCORES) {
                    float2 wv = __ldg(&((const float2*)tw)[lane]);
                    float dot = xr.x * wv.x + xr.y * wv.y;
                    float nsq = wv.x * wv.x + wv.y * wv.y;
                    for (int off = 16; off > 0; off >>= 1) {
                        dot += __shfl_xor_sync(0xFFFFFFFFu, dot, off);
                        nsq += __shfl_xor_sync(0xFFFFFFFFu, nsq, off);
                    }
                    if (lane == 0) g_S[n] = tanhf(dot * rsqrtf(nsq));
                }
            }
        }
    }
}

__device__ __forceinline__ unsigned long long make_key(float f, int idx) {
    unsigned u = __float_as_uint(f);
    u = (u & 0x80000000u) ? ~u : (u | 0x80000000u);
    return ((unsigned long long)u << 32) | (unsigned)(0xFFFFFFFFu - (unsigned)idx);
}

// ---------------- fused tail: per-graph radix-select + pool + linear -------
__global__ void k_tail(const float* __restrict__ lw, const float* __restrict__ lb,
                       float* __restrict__ out) {
    __shared__ int hist[256];
    __shared__ float sm[256];
    __shared__ float pooled[HH];
    __shared__ unsigned long long s_prefix;
    __shared__ int s_kk;
    int g = blockIdx.x;
    int t = threadIdx.x;

    if (t == 0) { s_prefix = 0ULL; s_kk = KKEEP; }
    __syncthreads();
    for (int pass = 7; pass >= 0; --pass) {
        int shift = pass * 8;
        hist[t] = 0;
        __syncthreads();
        unsigned long long pfx = s_prefix;
        unsigned long long maskhi = (pass == 7) ? 0ULL : ((~0ULL) << (shift + 8));
        for (int i = t; i < NPG; i += 256) {
            unsigned long long key = make_key(g_S[g * NPG + i], i);
            if ((key & maskhi) == (pfx & maskhi))
                atomicAdd(&hist[(int)((key >> shift) & 0xFF)], 1);
        }
        __syncthreads();
        if (t == 0) {
            int kk = s_kk;
            int bb = 255;
            for (;;) {
                int c = hist[bb];
                if (c >= kk) break;
                kk -= c;
                --bb;
            }
            s_kk = kk;
            s_prefix = pfx | ((unsigned long long)bb << shift);
        }
        __syncthreads();
    }
    unsigned long long thr = s_prefix;

    int ch = t & 63;
    int nl = t >> 6;
    float acc = 0.f;
    for (int i = nl; i < NPG; i += 4) {
        int node = g * NPG + i;
        float sv = g_S[node];
        if (make_key(sv, i) >= thr) {
            float2 f = h2_to_f2(g_XR[node * HC + (ch >> 1)]);
            acc += ((ch & 1) ? f.y : f.x) * sv;
        }
    }
    sm[t] = acc;
    __syncthreads();
    if (nl == 0)
        pooled[ch] = (sm[ch] + sm[64 + ch] + sm[128 + ch] + sm[192 + ch]) * (1.0f / (float)KKEEP);
    __syncthreads();

    if (t < 10) {
        float a = __ldg(&lb[t]);
        #pragma unroll
        for (int hh = 0; hh < HH; ++hh)
            a += pooled[hh] * __ldg(&lw[hh * 10 + t]);
        out[g * 10 + t] = a;
    }
}

// ---------------------------------------------------------------------------
extern "C" void kernel_launch(void* const* d_in, const int* in_sizes, int n_in,
                              void* d_out, int out_size) {
    const float* x     = (const float*)d_in[0];
    const int*   ei    = (const int*)d_in[1];
    const float* h     = (const float*)d_in[3];
    const float* alpha = (const float*)d_in[4];
    const float* c0    = (const float*)d_in[5];
    const float* cj    = (const float*)d_in[6];
    const float* tw    = (const float*)d_in[7];
    const float* lw    = (const float*)d_in[8];
    const float* lb    = (const float*)d_in[9];
    float* out = (float*)d_out;

    int dev = 0, nsm = 148;
    cudaGetDevice(&dev);
    cudaDeviceGetAttribute(&nsm, cudaDevAttrMultiProcessorCount, dev);
    const int SPMM_GRID = nsm * 6;     // grid-stride: ~7 nodes per warp, no wave tail

    // CSR build (both directions); k_zero also converts x -> fp16
    k_zero<<<1024, 256>>>(x);
    k_hist<<<1024, 256>>>(ei);
    k_scan<<<2, 1024>>>();
    k_fill<<<1024, 256>>>(ei);

    for (int l = 0; l < 2; ++l) {
        k_params<<<(NN + 255) / 256, 256>>>(h, alpha, l);
        for (int j = 0; j < 3; ++j) {
            if (j == 0)
                k_bj_real<<<SPMM_GRID, 256>>>(l, c0, l);
            else
                k_bj_cplx<<<SPMM_GRID, 256>>>();
            int cjoff = (l * 3 + j) * 2;
            k_jac<false, false, false><<<SPMM_GRID, 256>>>(0, 1, cj, cjoff, tw);
            k_jac<false, false, false><<<SPMM_GRID, 256>>>(1, 0, cj, cjoff, tw);
            k_jac<false, false, false><<<SPMM_GRID, 256>>>(0, 1, cj, cjoff, tw);
            if (j < 2)
                k_jac<true, false, false><<<SPMM_GRID, 256>>>(1, 0, cj, cjoff, tw);
            else if (l == 0)
                k_jac<true, true, false><<<SPMM_GRID, 256>>>(1, 0, cj, cjoff, tw);
            else
                k_jac<true, true, true><<<SPMM_GRID, 256>>>(1, 0, cj, cjoff, tw);
        }
    }

    k_tail<<<GG, 256>>>(lw, lb, out);
}

// round 11
// speedup vs baseline: 1.1401x; 1.1152x over previous
#include <cuda_runtime.h>
#include <cuda_fp16.h>

// ---------------------------------------------------------------------------
// CayleyNet: 2x CayleyConv (R=3, K=4 Jacobi) + TopKPooling(0.9) + mean pool + linear
// fp16 storage (z, y, BJ, x), fp32 accumulation, jw-folded Jacobi,
// fused relu/scores epilogues, identity scheduling, uint16 adjacency,
// both-layer params precomputed upfront, flat one-warp-per-node SpMM launches,
// fused select+pool+linear tail.
// ---------------------------------------------------------------------------

#define NN    50000
#define EE    800000
#define HH    64
#define HC    32          // lanes per node: lane = 2 complex channels
#define GG    10
#define NPG   5000
#define KKEEP 4500        // ceil(0.9 * 5000)

// ---------------- static device scratch (no allocations allowed) ----------
__device__ int g_cntR[NN];
__device__ int g_cntC[NN];
__device__ int g_rptr[NN + 1];
__device__ int g_cptr[NN + 1];
__device__ unsigned short g_adjR[EE];  // grouped by row: stores col (dst), ids < 65536
__device__ unsigned short g_adjC[EE];  // grouped by col: stores row (src)
__device__ float2 g_jw[2 * NN];        // h * tmp_left[n], both layers
__device__ float2 g_bd[2 * NN];        // b_dia[n], both layers
__device__ uint2  g_BJ[NN * HC];       // b_j (fp16 x4)
__device__ uint2  g_Z0[NN * HC];       // z = jw*y (fp16 x4) ping
__device__ uint2  g_Z1[NN * HC];       // z pong
__device__ uint2  g_Y16[NN * HC];      // final y per order (fp16 x4)
__device__ float2 g_OUT[NN * HC];      // real accumulator (fp32, 2 ch)
__device__ unsigned g_XH[NN * HC];     // fp16 copy of input x (packed half2)
__device__ unsigned g_XR[NN * HC];     // relu'd features (packed half2)
__device__ float  g_S[NN];             // topk scores
__device__ float g_pool[GG * HH];

__device__ __forceinline__ uint2* zbuf(int s) { return s ? g_Z1 : g_Z0; }

// register-friendly reinterpret helpers
union H4U { uint2 u; __half2 h[2]; };
union H2U { unsigned u; __half2 h; };

__device__ __forceinline__ float4 h4_to_f4(uint2 v) {
    H4U c; c.u = v;
    float2 fa = __half22float2(c.h[0]);
    float2 fb = __half22float2(c.h[1]);
    return make_float4(fa.x, fa.y, fb.x, fb.y);
}
__device__ __forceinline__ uint2 f4_to_h4(float4 f) {
    H4U c;
    c.h[0] = __float22half2_rn(make_float2(f.x, f.y));
    c.h[1] = __float22half2_rn(make_float2(f.z, f.w));
    return c.u;
}
__device__ __forceinline__ float2 h2_to_f2(unsigned v) {
    H2U c; c.u = v;
    return __half22float2(c.h);
}
__device__ __forceinline__ unsigned f2_to_h2(float2 f) {
    H2U c; c.h = __float22half2_rn(f);
    return c.u;
}

// ---------------- CSR init + x->fp16 (merged) ------------------------------
__global__ void k_zero(const float* __restrict__ x) {
    int stride = gridDim.x * blockDim.x;
    for (int i = blockIdx.x * blockDim.x + threadIdx.x; i < NN * HC; i += stride) {
        if (i < NN) { g_cntR[i] = 0; g_cntC[i] = 0; }
        float2 v = ((const float2*)x)[i];
        g_XH[i] = f2_to_h2(v);
    }
}

__global__ void k_hist(const int* __restrict__ ei) {
    for (int e = blockIdx.x * blockDim.x + threadIdx.x; e < EE; e += gridDim.x * blockDim.x) {
        atomicAdd(&g_cntR[ei[e]], 1);
        atomicAdd(&g_cntC[ei[EE + e]], 1);
    }
}

// 2 blocks: block 0 scans cntR->rptr, block 1 scans cntC->cptr.
// Also rewrites cnt[i] = start offset (fill cursor).
__global__ void k_scan() {
    __shared__ int sm[1024];
    const int PER = 49;
    int which = blockIdx.x;
    int* cnt = which ? g_cntC : g_cntR;
    int* ptr = which ? g_cptr : g_rptr;
    int t = threadIdx.x;
    int base = t * PER;
    int local = 0;
    for (int i = 0; i < PER; ++i) {
        int idx = base + i;
        if (idx < NN) local += cnt[idx];
    }
    sm[t] = local;
    __syncthreads();
    for (int off = 1; off < 1024; off <<= 1) {
        int v = (t >= off) ? sm[t - off] : 0;
        __syncthreads();
        sm[t] += v;
        __syncthreads();
    }
    int run = sm[t] - local;
    for (int i = 0; i < PER; ++i) {
        int idx = base + i;
        if (idx < NN) {
            int c = cnt[idx];
            ptr[idx] = run;
            cnt[idx] = run;     // cursor for k_fill
            run += c;
        }
    }
    if (t == 1023) ptr[NN] = sm[1023];
}

__global__ void k_fill(const int* __restrict__ ei) {
    for (int e = blockIdx.x * blockDim.x + threadIdx.x; e < EE; e += gridDim.x * blockDim.x) {
        int r = ei[e];
        int c = ei[EE + e];
        g_adjR[atomicAdd(&g_cntR[r], 1)] = (unsigned short)c;
        g_adjC[atomicAdd(&g_cntC[c], 1)] = (unsigned short)r;
    }
}

// ---------------- both layers' node parameters in one launch ---------------
__global__ void k_params2(const float* __restrict__ h, const float* __restrict__ alpha) {
    float h0 = h[0], a0 = alpha[0];
    float h1 = h[1], a1 = alpha[1];
    for (int n = blockIdx.x * blockDim.x + threadIdx.x; n < NN; n += gridDim.x * blockDim.x) {
        float deg = (float)(g_rptr[n + 1] - g_rptr[n]);
        float a = h0 * (deg - a0);
        float inv = 1.0f / (a * a + 1.0f);
        g_jw[n] = make_float2(h0 * a * inv, -h0 * inv);
        g_bd[n] = make_float2((a * a - 1.0f) * inv, -2.0f * a * inv);
        a = h1 * (deg - a1);
        inv = 1.0f / (a * a + 1.0f);
        g_jw[NN + n] = make_float2(h1 * a * inv, -h1 * inv);
        g_bd[NN + n] = make_float2((a * a - 1.0f) * inv, -2.0f * a * inv);
    }
}

// ---------------- b_j from REAL fp16 input (j==0): also init OUT, Z0 -------
__global__ void k_bj_real(int use_xr, const float* __restrict__ c0, int l) {
    int warp = (blockIdx.x * blockDim.x + threadIdx.x) >> 5;
    int lane = threadIdx.x & 31;
    if (warp >= NN) return;
    int n = warp;
    const unsigned* __restrict__ X = use_xr ? g_XR : g_XH;
    int p = g_rptr[n], end = g_rptr[n + 1];
    float sx = 0.f, sy = 0.f;
    for (; p + 8 <= end; p += 8) {
        int d0 = __ldg(&g_adjR[p + 0]), d1 = __ldg(&g_adjR[p + 1]);
        int d2 = __ldg(&g_adjR[p + 2]), d3 = __ldg(&g_adjR[p + 3]);
        int d4 = __ldg(&g_adjR[p + 4]), d5 = __ldg(&g_adjR[p + 5]);
        int d6 = __ldg(&g_adjR[p + 6]), d7 = __ldg(&g_adjR[p + 7]);
        float2 f0 = h2_to_f2(__ldg(&X[d0 * HC + lane]));
        float2 f1 = h2_to_f2(__ldg(&X[d1 * HC + lane]));
        float2 f2 = h2_to_f2(__ldg(&X[d2 * HC + lane]));
        float2 f3 = h2_to_f2(__ldg(&X[d3 * HC + lane]));
        float2 f4 = h2_to_f2(__ldg(&X[d4 * HC + lane]));
        float2 f5 = h2_to_f2(__ldg(&X[d5 * HC + lane]));
        float2 f6 = h2_to_f2(__ldg(&X[d6 * HC + lane]));
        float2 f7 = h2_to_f2(__ldg(&X[d7 * HC + lane]));
        sx += f0.x + f1.x + f2.x + f3.x + f4.x + f5.x + f6.x + f7.x;
        sy += f0.y + f1.y + f2.y + f3.y + f4.y + f5.y + f6.y + f7.y;
    }
    for (; p < end; ++p) {
        int d = __ldg(&g_adjR[p]);
        float2 f = h2_to_f2(__ldg(&X[d * HC + lane]));
        sx += f.x;
        sy += f.y;
    }
    float2 jwv = g_jw[l * NN + n];
    float wnx = -jwv.x, wny = -jwv.y;
    float2 bdv = g_bd[l * NN + n];
    float2 vn = h2_to_f2(__ldg(&X[n * HC + lane]));
    float4 b;
    b.x = wnx * sx + bdv.x * vn.x;
    b.y = wny * sx + bdv.y * vn.x;
    b.z = wnx * sy + bdv.x * vn.y;
    b.w = wny * sy + bdv.y * vn.y;
    int idx = n * HC + lane;
    g_BJ[idx] = f4_to_h4(b);
    float4 z;                              // z0 = jw * b
    z.x = jwv.x * b.x - jwv.y * b.y;
    z.y = jwv.x * b.y + jwv.y * b.x;
    z.z = jwv.x * b.z - jwv.y * b.w;
    z.w = jwv.x * b.w + jwv.y * b.z;
    g_Z0[idx] = f4_to_h4(z);
    float c0v = __ldg(&c0[l]);
    g_OUT[idx] = make_float2(c0v * vn.x, c0v * vn.y);
}

// ---------------- b_j from COMPLEX fp16 input (j>0): reads Y16 -------------
__global__ void k_bj_cplx(int l) {
    int warp = (blockIdx.x * blockDim.x + threadIdx.x) >> 5;
    int lane = threadIdx.x & 31;
    if (warp >= NN) return;
    int n = warp;
    int p = g_rptr[n], end = g_rptr[n + 1];
    float4 a = make_float4(0.f, 0.f, 0.f, 0.f);
    for (; p + 8 <= end; p += 8) {
        int d0 = __ldg(&g_adjR[p + 0]), d1 = __ldg(&g_adjR[p + 1]);
        int d2 = __ldg(&g_adjR[p + 2]), d3 = __ldg(&g_adjR[p + 3]);
        int d4 = __ldg(&g_adjR[p + 4]), d5 = __ldg(&g_adjR[p + 5]);
        int d6 = __ldg(&g_adjR[p + 6]), d7 = __ldg(&g_adjR[p + 7]);
        float4 v0 = h4_to_f4(__ldg(&g_Y16[d0 * HC + lane]));
        float4 v1 = h4_to_f4(__ldg(&g_Y16[d1 * HC + lane]));
        float4 v2 = h4_to_f4(__ldg(&g_Y16[d2 * HC + lane]));
        float4 v3 = h4_to_f4(__ldg(&g_Y16[d3 * HC + lane]));
        float4 v4 = h4_to_f4(__ldg(&g_Y16[d4 * HC + lane]));
        float4 v5 = h4_to_f4(__ldg(&g_Y16[d5 * HC + lane]));
        float4 v6 = h4_to_f4(__ldg(&g_Y16[d6 * HC + lane]));
        float4 v7 = h4_to_f4(__ldg(&g_Y16[d7 * HC + lane]));
        a.x += v0.x + v1.x + v2.x + v3.x + v4.x + v5.x + v6.x + v7.x;
        a.y += v0.y + v1.y + v2.y + v3.y + v4.y + v5.y + v6.y + v7.y;
        a.z += v0.z + v1.z + v2.z + v3.z + v4.z + v5.z + v6.z + v7.z;
        a.w += v0.w + v1.w + v2.w + v3.w + v4.w + v5.w + v6.w + v7.w;
    }
    for (; p < end; ++p) {
        int d = __ldg(&g_adjR[p]);
        float4 v = h4_to_f4(__ldg(&g_Y16[d * HC + lane]));
        a.x += v.x; a.y += v.y; a.z += v.z; a.w += v.w;
    }
    float2 jwv = g_jw[l * NN + n];
    float wnx = -jwv.x, wny = -jwv.y;
    float2 bdv = g_bd[l * NN + n];
    int idx = n * HC + lane;
    float4 vn = h4_to_f4(g_Y16[idx]);
    float4 b;
    b.x = wnx * a.x - wny * a.y + bdv.x * vn.x - bdv.y * vn.y;
    b.y = wnx * a.y + wny * a.x + bdv.x * vn.y + bdv.y * vn.x;
    b.z = wnx * a.z - wny * a.w + bdv.x * vn.z - bdv.y * vn.w;
    b.w = wnx * a.w + wny * a.z + bdv.x * vn.w + bdv.y * vn.z;
    g_BJ[idx] = f4_to_h4(b);
    float4 z;
    z.x = jwv.x * b.x - jwv.y * b.y;
    z.y = jwv.x * b.y + jwv.y * b.x;
    z.z = jwv.x * b.z - jwv.y * b.w;
    z.w = jwv.x * b.w + jwv.y * b.z;
    g_Z0[idx] = f4_to_h4(z);
}

// ---------------- jacobi: y[n] = sum_{e:col=n} z[src] + b_j[n] -------------
// FINAL=false: write z_out = jw*y.
// FINAL,!LAST: write Y16=y, OUT += 2*Re(cj*y).
// FINAL,LAST : o = OUT + 2*Re(cj*y); XR = relu(o) fp16; SCORES: also g_S.
template <bool FINAL, bool LAST, bool SCORES>
__global__ void k_jac(int in_sel, int out_sel, const float* __restrict__ cj, int cjoff,
                      const float* __restrict__ tw, int l) {
    int warp = (blockIdx.x * blockDim.x + threadIdx.x) >> 5;
    int lane = threadIdx.x & 31;
    if (warp >= NN) return;
    int n = warp;
    const uint2* __restrict__ Zin = zbuf(in_sel);
    int p = g_cptr[n], end = g_cptr[n + 1];
    float4 acc = make_float4(0.f, 0.f, 0.f, 0.f);
    for (; p + 8 <= end; p += 8) {
        int s0 = __ldg(&g_adjC[p + 0]), s1 = __ldg(&g_adjC[p + 1]);
        int s2 = __ldg(&g_adjC[p + 2]), s3 = __ldg(&g_adjC[p + 3]);
        int s4 = __ldg(&g_adjC[p + 4]), s5 = __ldg(&g_adjC[p + 5]);
        int s6 = __ldg(&g_adjC[p + 6]), s7 = __ldg(&g_adjC[p + 7]);
        float4 v0 = h4_to_f4(__ldg(&Zin[s0 * HC + lane]));
        float4 v1 = h4_to_f4(__ldg(&Zin[s1 * HC + lane]));
        float4 v2 = h4_to_f4(__ldg(&Zin[s2 * HC + lane]));
        float4 v3 = h4_to_f4(__ldg(&Zin[s3 * HC + lane]));
        float4 v4 = h4_to_f4(__ldg(&Zin[s4 * HC + lane]));
        float4 v5 = h4_to_f4(__ldg(&Zin[s5 * HC + lane]));
        float4 v6 = h4_to_f4(__ldg(&Zin[s6 * HC + lane]));
        float4 v7 = h4_to_f4(__ldg(&Zin[s7 * HC + lane]));
        acc.x += v0.x + v1.x + v2.x + v3.x + v4.x + v5.x + v6.x + v7.x;
        acc.y += v0.y + v1.y + v2.y + v3.y + v4.y + v5.y + v6.y + v7.y;
        acc.z += v0.z + v1.z + v2.z + v3.z + v4.z + v5.z + v6.z + v7.z;
        acc.w += v0.w + v1.w + v2.w + v3.w + v4.w + v5.w + v6.w + v7.w;
    }
    for (; p < end; ++p) {
        int s = __ldg(&g_adjC[p]);
        float4 v = h4_to_f4(__ldg(&Zin[s * HC + lane]));
        acc.x += v.x; acc.y += v.y; acc.z += v.z; acc.w += v.w;
    }
    int idx = n * HC + lane;
    float4 b = h4_to_f4(g_BJ[idx]);
    acc.x += b.x; acc.y += b.y; acc.z += b.z; acc.w += b.w;   // acc = y
    if (!FINAL) {
        float2 jwv = g_jw[l * NN + n];
        float4 z;
        z.x = jwv.x * acc.x - jwv.y * acc.y;
        z.y = jwv.x * acc.y + jwv.y * acc.x;
        z.z = jwv.x * acc.z - jwv.y * acc.w;
        z.w = jwv.x * acc.w + jwv.y * acc.z;
        zbuf(out_sel)[idx] = f4_to_h4(z);
    } else {
        float cr = __ldg(&cj[cjoff]), ci = __ldg(&cj[cjoff + 1]);
        float2 o = g_OUT[idx];
        o.x += 2.0f * (cr * acc.x - ci * acc.y);
        o.y += 2.0f * (cr * acc.z - ci * acc.w);
        if (!LAST) {
            g_Y16[idx] = f4_to_h4(acc);
            g_OUT[idx] = o;
        } else {
            float2 xr = make_float2(fmaxf(o.x, 0.f), fmaxf(o.y, 0.f));
            g_XR[idx] = f2_to_h2(xr);
            if (SCORES) {
                float2 wv = __ldg(&((const float2*)tw)[lane]);
                float dot = xr.x * wv.x + xr.y * wv.y;
                float nsq = wv.x * wv.x + wv.y * wv.y;
                for (int off = 16; off > 0; off >>= 1) {
                    dot += __shfl_xor_sync(0xFFFFFFFFu, dot, off);
                    nsq += __shfl_xor_sync(0xFFFFFFFFu, nsq, off);
                }
                if (lane == 0) g_S[n] = tanhf(dot * rsqrtf(nsq));
            }
        }
    }
}

__device__ __forceinline__ unsigned long long make_key(float f, int idx) {
    unsigned u = __float_as_uint(f);
    u = (u & 0x80000000u) ? ~u : (u | 0x80000000u);
    return ((unsigned long long)u << 32) | (unsigned)(0xFFFFFFFFu - (unsigned)idx);
}

// ---------------- fused tail: per-graph radix-select + pool + linear -------
__global__ void k_tail(const float* __restrict__ lw, const float* __restrict__ lb,
                       float* __restrict__ out) {
    __shared__ int hist[256];
    __shared__ float sm[256];
    __shared__ float pooled[HH];
    __shared__ unsigned long long s_prefix;
    __shared__ int s_kk;
    int g = blockIdx.x;
    int t = threadIdx.x;

    if (t == 0) { s_prefix = 0ULL; s_kk = KKEEP; }
    __syncthreads();
    for (int pass = 7; pass >= 0; --pass) {
        int shift = pass * 8;
        hist[t] = 0;
        __syncthreads();
        unsigned long long pfx = s_prefix;
        unsigned long long maskhi = (pass == 7) ? 0ULL : ((~0ULL) << (shift + 8));
        for (int i = t; i < NPG; i += 256) {
            unsigned long long key = make_key(g_S[g * NPG + i], i);
            if ((key & maskhi) == (pfx & maskhi))
                atomicAdd(&hist[(int)((key >> shift) & 0xFF)], 1);
        }
        __syncthreads();
        if (t == 0) {
            int kk = s_kk;
            int bb = 255;
            for (;;) {
                int c = hist[bb];
                if (c >= kk) break;
                kk -= c;
                --bb;
            }
            s_kk = kk;
            s_prefix = pfx | ((unsigned long long)bb << shift);
        }
        __syncthreads();
    }
    unsigned long long thr = s_prefix;

    int ch = t & 63;
    int nl = t >> 6;
    float acc = 0.f;
    for (int i = nl; i < NPG; i += 4) {
        int node = g * NPG + i;
        float sv = g_S[node];
        if (make_key(sv, i) >= thr) {
            float2 f = h2_to_f2(g_XR[node * HC + (ch >> 1)]);
            acc += ((ch & 1) ? f.y : f.x) * sv;
        }
    }
    sm[t] = acc;
    __syncthreads();
    if (nl == 0)
        pooled[ch] = (sm[ch] + sm[64 + ch] + sm[128 + ch] + sm[192 + ch]) * (1.0f / (float)KKEEP);
    __syncthreads();

    if (t < 10) {
        float a = __ldg(&lb[t]);
        #pragma unroll
        for (int hh = 0; hh < HH; ++hh)
            a += pooled[hh] * __ldg(&lw[hh * 10 + t]);
        out[g * 10 + t] = a;
    }
}

// ---------------------------------------------------------------------------
extern "C" void kernel_launch(void* const* d_in, const int* in_sizes, int n_in,
                              void* d_out, int out_size) {
    const float* x     = (const float*)d_in[0];
    const int*   ei    = (const int*)d_in[1];
    const float* h     = (const float*)d_in[3];
    const float* alpha = (const float*)d_in[4];
    const float* c0    = (const float*)d_in[5];
    const float* cj    = (const float*)d_in[6];
    const float* tw    = (const float*)d_in[7];
    const float* lw    = (const float*)d_in[8];
    const float* lb    = (const float*)d_in[9];
    float* out = (float*)d_out;

    const int SPMM_GRID = (NN * 32 + 255) / 256;   // flat: one warp per node

    // CSR build (both directions); k_zero also converts x -> fp16
    k_zero<<<1024, 256>>>(x);
    k_hist<<<1024, 256>>>(ei);
    k_scan<<<2, 1024>>>();
    k_fill<<<1024, 256>>>(ei);
    k_params2<<<(NN + 255) / 256, 256>>>(h, alpha);

    for (int l = 0; l < 2; ++l) {
        for (int j = 0; j < 3; ++j) {
            if (j == 0)
                k_bj_real<<<SPMM_GRID, 256>>>(l, c0, l);
            else
                k_bj_cplx<<<SPMM_GRID, 256>>>(l);
            int cjoff = (l * 3 + j) * 2;
            k_jac<false, false, false><<<SPMM_GRID, 256>>>(0, 1, cj, cjoff, tw, l);
            k_jac<false, false, false><<<SPMM_GRID, 256>>>(1, 0, cj, cjoff, tw, l);
            k_jac<false, false, false><<<SPMM_GRID, 256>>>(0, 1, cj, cjoff, tw, l);
            if (j < 2)
                k_jac<true, false, false><<<SPMM_GRID, 256>>>(1, 0, cj, cjoff, tw, l);
            else if (l == 0)
                k_jac<true, true, false><<<SPMM_GRID, 256>>>(1, 0, cj, cjoff, tw, l);
            else
                k_jac<true, true, true><<<SPMM_GRID, 256>>>(1, 0, cj, cjoff, tw, l);
        }
    }

    k_tail<<<GG, 256>>>(lw, lb, out);
}